// round 15
// baseline (speedup 1.0000x reference)
#include <cuda_runtime.h>
#include <cuda_fp16.h>
#include <cstdint>

#define Bn 8192
#define En 16
#define Zn 256
#define Hn 1024
#define Un 256
#define TM 64
#define MAXT 144
#define NT 512
#define KC 64
#define LDA 264                    // A smem row stride (halves)
#define TILEB 16384                // one B chunk: 128 rows x 64 halves, swizzled
#define TPE 48                     // tiles per expert: Wz 8, Wh 32, Wu 8

// smem byte offsets
#define OAZ 0                      // z tile / later u tile
#define OA2 33792                  // a tile
#define OBS 67584                  // B rings: group g at OBS + g*3*TILEB
#define SMEM_DYN (OBS + 6*TILEB)   // 165888

// ---------------- device scratch ----------------
__device__ int g_perm[Bn];
__device__ int g_te[MAXT], g_ts[MAXT], g_tr[MAXT];
__device__ int g_tj[MAXT], g_tJ[MAXT];
__device__ int g_ntiles;
__device__ int g_done[En];                         // per-expert conversion counter
__device__ __half g_Wt[(size_t)En * TPE * 8192];   // tiled+swizzled fp16 weights

// ---------------- helpers ----------------
__device__ __forceinline__ uint32_t s2u(const void* p) {
    uint32_t a;
    asm("{ .reg .u64 t; cvta.to.shared.u64 t, %1; cvt.u32.u64 %0, t; }" : "=r"(a) : "l"(p));
    return a;
}
__device__ __forceinline__ void mbar_init(uint32_t a, uint32_t c) {
    asm volatile("mbarrier.init.shared.b64 [%0], %1;" :: "r"(a), "r"(c) : "memory");
}
__device__ __forceinline__ void mbar_expect(uint32_t a, uint32_t bytes) {
    asm volatile("mbarrier.arrive.expect_tx.shared.b64 _, [%0], %1;" :: "r"(a), "r"(bytes) : "memory");
}
__device__ __forceinline__ void bulk_g2s(uint32_t dst, const void* src, uint32_t bytes, uint32_t mbar) {
    asm volatile("cp.async.bulk.shared::cluster.global.mbarrier::complete_tx::bytes [%0], [%1], %2, [%3];"
                 :: "r"(dst), "l"(src), "r"(bytes), "r"(mbar) : "memory");
}
__device__ __forceinline__ void mwait(uint32_t a, uint32_t par) {
    uint32_t done = 0;
    while (!done) {
        asm volatile("{ .reg .pred p; mbarrier.try_wait.parity.acquire.cta.shared::cta.b64 p, [%1], %2; selp.b32 %0, 1, 0, p; }"
                     : "=r"(done) : "r"(a), "r"(par) : "memory");
    }
}
__device__ __forceinline__ void gbar(int id) {
    asm volatile("bar.sync %0, 256;" :: "r"(id) : "memory");
}
__device__ __forceinline__ void fence_pa() {
    asm volatile("fence.proxy.async;" ::: "memory");
}
__device__ __forceinline__ void ldm4(uint32_t r[4], uint32_t addr) {
    asm volatile("ldmatrix.sync.aligned.m8n8.x4.shared.b16 {%0,%1,%2,%3}, [%4];"
                 : "=r"(r[0]), "=r"(r[1]), "=r"(r[2]), "=r"(r[3]) : "r"(addr));
}
__device__ __forceinline__ void mma16816(float c[4], const uint32_t a[4], uint32_t b0, uint32_t b1) {
    asm volatile("mma.sync.aligned.m16n8k16.row.col.f32.f16.f16.f32 "
                 "{%0,%1,%2,%3}, {%4,%5,%6,%7}, {%8,%9}, {%0,%1,%2,%3};"
                 : "+f"(c[0]), "+f"(c[1]), "+f"(c[2]), "+f"(c[3])
                 : "r"(a[0]), "r"(a[1]), "r"(a[2]), "r"(a[3]), "r"(b0), "r"(b1));
}
__device__ __forceinline__ uint32_t swB(uint32_t r, uint32_t c16) {
    return (r << 7) + (((c16) ^ (r & 7)) << 4);
}

// convert one 16B dest unit of swizzled weight tile 'id/1024', unit 'id%1024'
__device__ __forceinline__ void cvt_unit(int id, const float* __restrict__ Wz,
                                         const float* __restrict__ Wh,
                                         const float* __restrict__ Wu) {
    const int t = id >> 10;
    const int w = id & 1023;
    const int r = w >> 3, c16s = w & 7;
    const int e = t / TPE, s = t % TPE;
    const float* src; int nc, kc;
    if (s < 8)       { src = Wz + (size_t)e * Zn * Zn; nc = s >> 2;        kc = s & 3; }
    else if (s < 40) { src = Wh + (size_t)e * Hn * Zn; nc = (s - 8) >> 2;  kc = (s - 8) & 3; }
    else             { src = Wu + (size_t)e * Un * Un; nc = (s - 40) >> 2; kc = (s - 40) & 3; }
    const int n = nc * 128 + r;
    const int k = kc * 64 + ((c16s ^ (r & 7)) << 3);
    const float4* sp = (const float4*)(src + (size_t)n * 256 + k);
    const float4 v0 = __ldg(sp), v1 = __ldg(sp + 1);
    union { __half2 h[4]; uint4 q; } P;
    P.h[0] = __floats2half2_rn(v0.x, v0.y);
    P.h[1] = __floats2half2_rn(v0.z, v0.w);
    P.h[2] = __floats2half2_rn(v1.x, v1.y);
    P.h[3] = __floats2half2_rn(v1.z, v1.w);
    *(uint4*)((char*)g_Wt + (size_t)t * TILEB + (uint32_t)((r << 7) + (c16s << 4))) = P.q;
}

// ---------------- k_setup: single block — buckets, tile list, counters ----------------
__global__ __launch_bounds__(1024) void k_setup(const int* __restrict__ rng) {
    __shared__ int srng[Bn];
    __shared__ int sc[En], soff[En], scur[En];
    const int tid = threadIdx.x, lane = tid & 31;
    for (int i = tid; i < Bn; i += 1024) srng[i] = rng[i];
    if (tid < En) { sc[tid] = 0; scur[tid] = 0; g_done[tid] = 0; }
    __syncthreads();
    for (int i = tid; i < Bn; i += 1024) {
        int e = srng[i];
        unsigned m = __match_any_sync(0xffffffffu, e);
        if (lane == __ffs(m) - 1) atomicAdd(&sc[e], __popc(m));
    }
    __syncthreads();
    if (tid == 0) {
        int acc = 0, nt = 0;
        for (int e = 0; e < En; e++) {
            soff[e] = acc;
            int c = sc[e];
            int J = (c + TM - 1) / TM;
            int j = 0;
            for (int s = 0; s < c; s += TM) {
                g_te[nt] = e;
                g_ts[nt] = acc + s;
                g_tr[nt] = (c - s) < TM ? (c - s) : TM;
                g_tj[nt] = j++;
                g_tJ[nt] = J;
                nt++;
            }
            acc += c;
        }
        g_ntiles = nt;
    }
    __syncthreads();
    for (int i = tid; i < Bn; i += 1024) {
        int e = srng[i];
        unsigned m = __match_any_sync(0xffffffffu, e);
        int leader = __ffs(m) - 1;
        int rank = __popc(m & ((1u << lane) - 1u));
        int base = 0;
        if (lane == leader) base = atomicAdd(&scur[e], __popc(m));
        base = __shfl_sync(0xffffffffu, base, leader);
        g_perm[soff[e] + base + rank] = i;
    }
}

// ---------------- A staging: gathered fp32 rows -> fp16 smem (all 512 thr) ----------------
__device__ __forceinline__ void stage_a32(char* smc, int off, const float* __restrict__ g,
                                          const int* ss, int tid) {
#pragma unroll
    for (int i = tid; i < TM * 32; i += NT) {
        int r = i >> 5, c = (i & 31) << 3;
        int s = ss[r];
        uint4 q = make_uint4(0u, 0u, 0u, 0u);
        if (s >= 0) {
            const float4 v0 = __ldg((const float4*)(g + (size_t)s * 256 + c));
            const float4 v1 = __ldg((const float4*)(g + (size_t)s * 256 + c + 4));
            union { __half2 h[4]; uint4 u; } P;
            P.h[0] = __floats2half2_rn(v0.x, v0.y);
            P.h[1] = __floats2half2_rn(v0.z, v0.w);
            P.h[2] = __floats2half2_rn(v1.x, v1.y);
            P.h[3] = __floats2half2_rn(v1.z, v1.w);
            q = P.u;
        }
        *(uint4*)(smc + off + (uint32_t)(r * LDA + c) * 2) = q;
    }
}

// ---------------- group GEMM: one 64x128 output chunk per call ----------------
// B chunks arrive via cp.async.bulk (producer tidg==0) + mbarrier. Global chunk
// counter ck = ck0+kc; buffer = ck%3, parity = (ck/3)&1. First call's chunk 0
// is prestaged in the prologue; later calls' chunk 0 staged by predecessor.
__device__ __forceinline__ void gemm_nc(uint32_t aB, uint32_t obsg, uint32_t mb, int gid,
                                        int ck0,
                                        const __half* __restrict__ gB,
                                        const __half* __restrict__ gBnext,
                                        float c[2][4][4], int tidg) {
    const int lane = tidg & 31, wig = tidg >> 5;
    const int wm = wig >> 2, wn = wig & 3;
    const int lrow = (lane & 7) + ((lane >> 3) & 1) * 8;
    const int lk8  = (lane >> 4) * 8;
    const int l16  = lane >> 4;

#pragma unroll
    for (int mt = 0; mt < 2; mt++)
#pragma unroll
        for (int nt = 0; nt < 4; nt++)
#pragma unroll
            for (int j = 0; j < 4; j++) c[mt][nt][j] = 0.f;

#pragma unroll
    for (int kc = 0; kc < 4; kc++) {
        const int ck = ck0 + kc;
        const __half* nsrc = (kc < 3) ? (gB + (size_t)(kc + 1) * 8192) : gBnext;
        if (nsrc && tidg == 0) {
            const uint32_t b1 = (uint32_t)((ck + 1) % 3);
            mbar_expect(mb + b1 * 8, TILEB);
            bulk_g2s(obsg + b1 * TILEB, nsrc, TILEB, mb + b1 * 8);
        }
        mwait(mb + (uint32_t)(ck % 3) * 8, (uint32_t)((ck / 3) & 1));
        gbar(1 + gid);

        const uint32_t bH = obsg + (uint32_t)(ck % 3) * TILEB;
#pragma unroll
        for (int k16 = 0; k16 < 4; k16++) {
            const int ka = kc * KC + k16 * 16 + lk8;
            uint32_t ah[2][4];
#pragma unroll
            for (int mt = 0; mt < 2; mt++)
                ldm4(ah[mt], aB + (uint32_t)((wm * 32 + mt * 16 + lrow) * LDA + ka) * 2);
            uint32_t bf[2][4];
#pragma unroll
            for (int ng = 0; ng < 2; ng++)
                ldm4(bf[ng], bH + swB((uint32_t)(wn * 32 + ng * 16 + lrow),
                                      (uint32_t)(k16 * 2 + l16)));
#pragma unroll
            for (int mt = 0; mt < 2; mt++)
#pragma unroll
                for (int nt = 0; nt < 4; nt++)
                    mma16816(c[mt][nt], ah[mt], bf[nt >> 1][nt & 1], bf[nt >> 1][(nt & 1) + 2]);
        }
    }
}

// ---------------- fused MoE kernel: inline weight cvt + bulk-staged GEMMs ----------------
__global__ __launch_bounds__(NT, 1)
void k_moe(const float* __restrict__ z, const float* __restrict__ u,
           const float* __restrict__ Wz, const float* __restrict__ Wh,
           const float* __restrict__ Wu,
           const float* __restrict__ bz, const float* __restrict__ bhb,
           float* __restrict__ out) {
    const int bt = blockIdx.x;
    if (bt >= g_ntiles) return;
    const int e = g_te[bt], start = g_ts[bt], rows = g_tr[bt];
    const int jr = g_tj[bt], J = g_tJ[bt];
    const int tid = threadIdx.x;
    const int gid = tid >> 8;
    const int tidg = tid & 255;
    const int lane = tid & 31, wig = tidg >> 5;
    const int wm = wig >> 2, wn = wig & 3;
    const int t4 = lane >> 2, t2 = (lane & 3) * 2;

    extern __shared__ char smc[];
    const uint32_t sm0 = s2u(smc);
    const uint32_t aZ = sm0 + OAZ, a2 = sm0 + OA2;
    const uint32_t obsg = sm0 + OBS + (uint32_t)gid * 3 * TILEB;

    __shared__ __align__(8) unsigned long long s_mb[6];
    const uint32_t mb = s2u(s_mb) + (uint32_t)gid * 24;

    __shared__ int ss[TM];
    if (tid < TM) ss[tid] = (tid < rows) ? g_perm[start + tid] : -1;
    if (tid < 6) mbar_init(s2u(s_mb) + tid * 8, 1);
    __syncthreads();

    // ---- inline weight conversion: this CTA converts tiles {s : s % J == jr} ----
    for (int s = jr; s < TPE; s += J) {
        const int base = (e * TPE + s) * 1024;
        cvt_unit(base + tid, Wz, Wh, Wu);
        cvt_unit(base + tid + NT, Wz, Wh, Wu);
    }
    __syncthreads();
    __threadfence();
    if (tid == 0) {
        atomicAdd(&g_done[e], 1);
        while (*(volatile int*)&g_done[e] < J) { }   // wait for sibling CTAs
    }
    __syncthreads();
    fence_pa();

    // per-group tile-base pointers for the 6 gemm calls
    const __half* Wbase = g_Wt + (size_t)e * TPE * 8192;
    const __half* callB[6];
    callB[0] = Wbase + (size_t)(0  + gid * 4) * 8192;
#pragma unroll
    for (int j = 0; j < 4; j++)
        callB[1 + j] = Wbase + (size_t)(8 + (j * 2 + gid) * 4) * 8192;
    callB[5] = Wbase + (size_t)(40 + gid * 4) * 8192;

    // prologue: prestage chunk 0 of call 0
    if (tidg == 0) {
        mbar_expect(mb, TILEB);
        bulk_g2s(obsg, callB[0], TILEB, mb);
    }

    stage_a32(smc, OAZ, z, ss, tid);
    __syncthreads();

    float c[2][4][4];

    // ---- GEMM1: a = z @ Wz^T + bz -> a2 (fp16); group N-half ----
    {
        const int n0 = gid * 128;
        gemm_nc(aZ, obsg, mb, gid, 0, callB[0], callB[1], c, tidg);
        const float* bzp = bz + (size_t)e * Zn + n0;
#pragma unroll
        for (int mt = 0; mt < 2; mt++) {
            const int r0 = wm * 32 + mt * 16 + t4;
#pragma unroll
            for (int nt = 0; nt < 4; nt++) {
                const int col = wn * 32 + nt * 8 + t2;
                const float2 bb = *(const float2*)(bzp + col);
                uint32_t o = (uint32_t)(r0 * LDA + n0 + col) * 2;
                *(__half2*)(smc + OA2 + o) = __floats2half2_rn(c[mt][nt][0] + bb.x, c[mt][nt][1] + bb.y);
                o = (uint32_t)((r0 + 8) * LDA + n0 + col) * 2;
                *(__half2*)(smc + OA2 + o) = __floats2half2_rn(c[mt][nt][2] + bb.x, c[mt][nt][3] + bb.y);
            }
        }
    }
    __syncthreads();

    stage_a32(smc, OAZ, u, ss, tid);
    __syncthreads();

    // ---- GEMM2: h = relu(a @ Wh^T + bh) -> out ----
    {
        for (int nc = 0; nc < 4; nc++) {
            const int n0 = nc * 256 + gid * 128;
            gemm_nc(a2, obsg, mb, gid, (1 + nc) * 4, callB[1 + nc], callB[2 + nc], c, tidg);
            const float* bhp = bhb + (size_t)e * Hn + n0;
#pragma unroll
            for (int mt = 0; mt < 2; mt++) {
                const int r0 = wm * 32 + mt * 16 + t4;
                const int s0 = ss[r0], s1 = ss[r0 + 8];
#pragma unroll
                for (int nt = 0; nt < 4; nt++) {
                    const int col = wn * 32 + nt * 8 + t2;
                    const float2 bb = *(const float2*)(bhp + col);
                    if (s0 >= 0) {
                        float2 o;
                        o.x = fmaxf(c[mt][nt][0] + bb.x, 0.f);
                        o.y = fmaxf(c[mt][nt][1] + bb.y, 0.f);
                        *(float2*)(out + (size_t)s0 * Hn + n0 + col) = o;
                    }
                    if (s1 >= 0) {
                        float2 o;
                        o.x = fmaxf(c[mt][nt][2] + bb.x, 0.f);
                        o.y = fmaxf(c[mt][nt][3] + bb.y, 0.f);
                        *(float2*)(out + (size_t)s1 * Hn + n0 + col) = o;
                    }
                }
            }
        }
    }

    // ---- GEMM3: v = u @ Wu^T -> out + Bn*Hn ----
    {
        const int n0 = gid * 128;
        float* outv = out + (size_t)Bn * Hn;
        gemm_nc(aZ, obsg, mb, gid, 20, callB[5], nullptr, c, tidg);
#pragma unroll
        for (int mt = 0; mt < 2; mt++) {
            const int r0 = wm * 32 + mt * 16 + t4;
            const int s0 = ss[r0], s1 = ss[r0 + 8];
#pragma unroll
            for (int nt = 0; nt < 4; nt++) {
                const int col = wn * 32 + nt * 8 + t2;
                if (s0 >= 0) {
                    float2 o; o.x = c[mt][nt][0]; o.y = c[mt][nt][1];
                    *(float2*)(outv + (size_t)s0 * Un + n0 + col) = o;
                }
                if (s1 >= 0) {
                    float2 o; o.x = c[mt][nt][2]; o.y = c[mt][nt][3];
                    *(float2*)(outv + (size_t)s1 * Un + n0 + col) = o;
                }
            }
        }
    }
}

// ---------------- launcher ----------------
extern "C" void kernel_launch(void* const* d_in, const int* in_sizes, int n_in,
                              void* d_out, int out_size) {
    (void)in_sizes; (void)n_in; (void)out_size;
    const float* z   = (const float*)d_in[0];
    const float* u   = (const float*)d_in[1];
    const int*   rng = (const int*)d_in[2];
    const float* Wz  = (const float*)d_in[3];
    const float* bz  = (const float*)d_in[4];
    const float* Wh  = (const float*)d_in[5];
    const float* bh  = (const float*)d_in[6];
    const float* Wu  = (const float*)d_in[7];
    float* out = (float*)d_out;

    cudaFuncSetAttribute(k_moe, cudaFuncAttributeMaxDynamicSharedMemorySize, SMEM_DYN);

    k_setup<<<1, 1024>>>(rng);
    k_moe<<<MAXT, NT, SMEM_DYN>>>(z, u, Wz, Wh, Wu, bz, bh, out);
}

// round 16
// speedup vs baseline: 1.0971x; 1.0971x over previous
#include <cuda_runtime.h>
#include <cuda_fp16.h>
#include <cstdint>

#define Bn 8192
#define En 16
#define Zn 256
#define Hn 1024
#define Un 256
#define TM 64
#define MAXT 144
#define NT 512
#define NTPRE 512
#define LDA 264                    // A smem row stride (halves)
#define TILEB 16384                // 16KB sub-tile: 128 rows x 64 halves, swizzled
#define CHUNKB 32768               // KC=128 chunk = 2 adjacent sub-tiles
#define TPE 48                     // tiles per expert: Wz 8, Wh 32, Wu 8

// smem byte offsets
#define OAZ 0                      // z tile / later u tile
#define OA2 33792                  // a tile
#define OBS 67584                  // B buffers: group g at OBS + g*2*CHUNKB
#define SMEM_DYN (OBS + 4*CHUNKB)  // 198656

// ---------------- device scratch ----------------
__device__ int g_perm[Bn];
__device__ int g_te[MAXT], g_ts[MAXT], g_tr[MAXT];
__device__ int g_ntiles;
__device__ __half g_Wt[(size_t)En * TPE * 8192];   // tiled+swizzled fp16 weights

// ---------------- helpers ----------------
__device__ __forceinline__ uint32_t s2u(const void* p) {
    uint32_t a;
    asm("{ .reg .u64 t; cvta.to.shared.u64 t, %1; cvt.u32.u64 %0, t; }" : "=r"(a) : "l"(p));
    return a;
}
__device__ __forceinline__ void mbar_init(uint32_t a, uint32_t c) {
    asm volatile("mbarrier.init.shared.b64 [%0], %1;" :: "r"(a), "r"(c) : "memory");
}
__device__ __forceinline__ void mbar_expect(uint32_t a, uint32_t bytes) {
    asm volatile("mbarrier.arrive.expect_tx.shared.b64 _, [%0], %1;" :: "r"(a), "r"(bytes) : "memory");
}
__device__ __forceinline__ void bulk_g2s(uint32_t dst, const void* src, uint32_t bytes, uint32_t mbar) {
    asm volatile("cp.async.bulk.shared::cluster.global.mbarrier::complete_tx::bytes [%0], [%1], %2, [%3];"
                 :: "r"(dst), "l"(src), "r"(bytes), "r"(mbar) : "memory");
}
__device__ __forceinline__ void mwait(uint32_t a, uint32_t par) {
    uint32_t done = 0;
    while (!done) {
        asm volatile("{ .reg .pred p; mbarrier.try_wait.parity.acquire.cta.shared::cta.b64 p, [%1], %2; selp.b32 %0, 1, 0, p; }"
                     : "=r"(done) : "r"(a), "r"(par) : "memory");
    }
}
__device__ __forceinline__ void gbar(int id) {
    asm volatile("bar.sync %0, 256;" :: "r"(id) : "memory");
}
__device__ __forceinline__ void ldm4(uint32_t r[4], uint32_t addr) {
    asm volatile("ldmatrix.sync.aligned.m8n8.x4.shared.b16 {%0,%1,%2,%3}, [%4];"
                 : "=r"(r[0]), "=r"(r[1]), "=r"(r[2]), "=r"(r[3]) : "r"(addr));
}
__device__ __forceinline__ void mma16816(float c[4], const uint32_t a[4], uint32_t b0, uint32_t b1) {
    asm volatile("mma.sync.aligned.m16n8k16.row.col.f32.f16.f16.f32 "
                 "{%0,%1,%2,%3}, {%4,%5,%6,%7}, {%8,%9}, {%0,%1,%2,%3};"
                 : "+f"(c[0]), "+f"(c[1]), "+f"(c[2]), "+f"(c[3])
                 : "r"(a[0]), "r"(a[1]), "r"(a[2]), "r"(a[3]), "r"(b0), "r"(b1));
}
__device__ __forceinline__ uint32_t swB(uint32_t r, uint32_t c16) {
    return (r << 7) + (((c16) ^ (r & 7)) << 4);
}

// convert one 16B dest unit of swizzled weight tile 'id/1024', unit 'id%1024'
__device__ __forceinline__ void cvt_unit(int id, const float* __restrict__ Wz,
                                         const float* __restrict__ Wh,
                                         const float* __restrict__ Wu) {
    const int t = id >> 10;
    const int w = id & 1023;
    const int r = w >> 3, c16s = w & 7;
    const int e = t / TPE, s = t % TPE;
    const float* src; int nc, kc;
    if (s < 8)       { src = Wz + (size_t)e * Zn * Zn; nc = s >> 2;        kc = s & 3; }
    else if (s < 40) { src = Wh + (size_t)e * Hn * Zn; nc = (s - 8) >> 2;  kc = (s - 8) & 3; }
    else             { src = Wu + (size_t)e * Un * Un; nc = (s - 40) >> 2; kc = (s - 40) & 3; }
    const int n = nc * 128 + r;
    const int k = kc * 64 + ((c16s ^ (r & 7)) << 3);
    const float4* sp = (const float4*)(src + (size_t)n * 256 + k);
    const float4 v0 = __ldg(sp), v1 = __ldg(sp + 1);
    union { __half2 h[4]; uint4 q; } P;
    P.h[0] = __floats2half2_rn(v0.x, v0.y);
    P.h[1] = __floats2half2_rn(v0.z, v0.w);
    P.h[2] = __floats2half2_rn(v1.x, v1.y);
    P.h[3] = __floats2half2_rn(v1.z, v1.w);
    *(uint4*)((char*)g_Wt + (size_t)t * TILEB + (uint32_t)((r << 7) + (c16s << 4))) = P.q;
}

// ---------------- k_pre: fat cvt blocks (4 units/thread) + setup block ----------------
#define NUNITS (En*TPE*1024)       // 786432
#define CVB (NUNITS/(NTPRE*4))     // 384

__global__ __launch_bounds__(NTPRE) void k_pre(const int* __restrict__ rng,
                                               const float* __restrict__ Wz,
                                               const float* __restrict__ Wh,
                                               const float* __restrict__ Wu) {
    if (blockIdx.x == CVB) {
        __shared__ int srng[Bn];
        __shared__ int sc[En], soff[En], scur[En];
        const int tid = threadIdx.x, lane = tid & 31;
        for (int i = tid; i < Bn; i += NTPRE) srng[i] = rng[i];
        if (tid < En) { sc[tid] = 0; scur[tid] = 0; }
        __syncthreads();
        for (int i = tid; i < Bn; i += NTPRE) {
            int e = srng[i];
            unsigned m = __match_any_sync(0xffffffffu, e);
            if (lane == __ffs(m) - 1) atomicAdd(&sc[e], __popc(m));
        }
        __syncthreads();
        if (tid == 0) {
            int acc = 0, nt = 0;
            for (int e = 0; e < En; e++) {
                soff[e] = acc;
                int c = sc[e];
                for (int s = 0; s < c; s += TM) {
                    g_te[nt] = e;
                    g_ts[nt] = acc + s;
                    g_tr[nt] = (c - s) < TM ? (c - s) : TM;
                    nt++;
                }
                acc += c;
            }
            g_ntiles = nt;
        }
        __syncthreads();
        for (int i = tid; i < Bn; i += NTPRE) {
            int e = srng[i];
            unsigned m = __match_any_sync(0xffffffffu, e);
            int leader = __ffs(m) - 1;
            int rank = __popc(m & ((1u << lane) - 1u));
            int base = 0;
            if (lane == leader) base = atomicAdd(&scur[e], __popc(m));
            base = __shfl_sync(0xffffffffu, base, leader);
            g_perm[soff[e] + base + rank] = i;
        }
        return;
    }
    const int base = blockIdx.x * (NTPRE * 4) + threadIdx.x;
    cvt_unit(base,             Wz, Wh, Wu);
    cvt_unit(base + NTPRE,     Wz, Wh, Wu);
    cvt_unit(base + 2 * NTPRE, Wz, Wh, Wu);
    cvt_unit(base + 3 * NTPRE, Wz, Wh, Wu);
}

// ---------------- A staging: gathered fp32 rows -> fp16 smem (all 512 thr) ----------------
__device__ __forceinline__ void stage_a32(char* smc, int off, const float* __restrict__ g,
                                          const int* ss, int tid) {
#pragma unroll
    for (int i = tid; i < TM * 32; i += NT) {
        int r = i >> 5, c = (i & 31) << 3;
        int s = ss[r];
        uint4 q = make_uint4(0u, 0u, 0u, 0u);
        if (s >= 0) {
            const float4 v0 = __ldg((const float4*)(g + (size_t)s * 256 + c));
            const float4 v1 = __ldg((const float4*)(g + (size_t)s * 256 + c + 4));
            union { __half2 h[4]; uint4 u; } P;
            P.h[0] = __floats2half2_rn(v0.x, v0.y);
            P.h[1] = __floats2half2_rn(v0.z, v0.w);
            P.h[2] = __floats2half2_rn(v1.x, v1.y);
            P.h[3] = __floats2half2_rn(v1.z, v1.w);
            q = P.u;
        }
        *(uint4*)(smc + off + (uint32_t)(r * LDA + c) * 2) = q;
    }
}

// ---------------- group GEMM: one 64x128 output chunk per call, KC=128 ----------------
// 2 chunks of 32KB per call; 2 buffers per group; global chunk index ck=ck0+kc,
// buffer=ck&1, parity=(ck>>1)&1. Producer (tidg==0) issues stage(ck+1) AFTER the
// group barrier (all warps past compute(ck-1), so overwriting buffer (ck+1)&1 is
// safe). First call's chunk 0 prestaged in prologue; later chunk0s chained.
__device__ __forceinline__ void gemm_nc(uint32_t aB, uint32_t obsg, uint32_t mb, int gid,
                                        int ck0,
                                        const __half* __restrict__ gB,
                                        const __half* __restrict__ gBnext,
                                        float c[2][4][4], int tidg) {
    const int lane = tidg & 31, wig = tidg >> 5;
    const int wm = wig >> 2, wn = wig & 3;
    const int lrow = (lane & 7) + ((lane >> 3) & 1) * 8;
    const int lk8  = (lane >> 4) * 8;
    const int l16  = lane >> 4;

#pragma unroll
    for (int mt = 0; mt < 2; mt++)
#pragma unroll
        for (int nt = 0; nt < 4; nt++)
#pragma unroll
            for (int j = 0; j < 4; j++) c[mt][nt][j] = 0.f;

#pragma unroll
    for (int kc = 0; kc < 2; kc++) {
        const int ck = ck0 + kc;
        mwait(mb + (uint32_t)(ck & 1) * 8, (uint32_t)((ck >> 1) & 1));
        gbar(1 + gid);
        const __half* nsrc = (kc == 0) ? (gB + 16384) : gBnext;
        if (nsrc && tidg == 0) {
            const uint32_t b1 = (uint32_t)((ck + 1) & 1);
            mbar_expect(mb + b1 * 8, CHUNKB);
            bulk_g2s(obsg + b1 * CHUNKB, nsrc, CHUNKB, mb + b1 * 8);
        }

        const uint32_t bH = obsg + (uint32_t)(ck & 1) * CHUNKB;
#pragma unroll
        for (int k16 = 0; k16 < 8; k16++) {
            const int ka = kc * 128 + k16 * 16 + lk8;
            uint32_t ah[2][4];
#pragma unroll
            for (int mt = 0; mt < 2; mt++)
                ldm4(ah[mt], aB + (uint32_t)((wm * 32 + mt * 16 + lrow) * LDA + ka) * 2);
            uint32_t bf[2][4];
            const uint32_t sub = bH + (uint32_t)(k16 >> 2) * TILEB;
#pragma unroll
            for (int ng = 0; ng < 2; ng++)
                ldm4(bf[ng], sub + swB((uint32_t)(wn * 32 + ng * 16 + lrow),
                                       (uint32_t)((k16 & 3) * 2 + l16)));
#pragma unroll
            for (int mt = 0; mt < 2; mt++)
#pragma unroll
                for (int nt = 0; nt < 4; nt++)
                    mma16816(c[mt][nt], ah[mt], bf[nt >> 1][nt & 1], bf[nt >> 1][(nt & 1) + 2]);
        }
    }
}

// ---------------- fused MoE kernel (2 groups, KC=128 bulk-staged B) ----------------
__global__ __launch_bounds__(NT, 1)
void k_moe(const float* __restrict__ z, const float* __restrict__ u,
           const float* __restrict__ bz, const float* __restrict__ bhb,
           float* __restrict__ out) {
    const int bt = blockIdx.x;
    if (bt >= g_ntiles) return;
    const int e = g_te[bt], start = g_ts[bt], rows = g_tr[bt];
    const int tid = threadIdx.x;
    const int gid = tid >> 8;
    const int tidg = tid & 255;
    const int lane = tid & 31, wig = tidg >> 5;
    const int wm = wig >> 2, wn = wig & 3;
    const int t4 = lane >> 2, t2 = (lane & 3) * 2;

    extern __shared__ char smc[];
    const uint32_t sm0 = s2u(smc);
    const uint32_t aZ = sm0 + OAZ, a2 = sm0 + OA2;
    const uint32_t obsg = sm0 + OBS + (uint32_t)gid * 2 * CHUNKB;

    __shared__ __align__(8) unsigned long long s_mb[4];
    const uint32_t mb = s2u(s_mb) + (uint32_t)gid * 16;

    __shared__ int ss[TM];
    if (tid < TM) ss[tid] = (tid < rows) ? g_perm[start + tid] : -1;
    if (tid < 4) mbar_init(s2u(s_mb) + tid * 8, 1);
    __syncthreads();

    // per-group base pointers for the 6 gemm calls (each call = 4 sub-tiles = 64KB)
    const __half* Wbase = g_Wt + (size_t)e * TPE * 8192;
    const __half* callB[6];
    callB[0] = Wbase + (size_t)(0  + gid * 4) * 8192;
#pragma unroll
    for (int j = 0; j < 4; j++)
        callB[1 + j] = Wbase + (size_t)(8 + (j * 2 + gid) * 4) * 8192;
    callB[5] = Wbase + (size_t)(40 + gid * 4) * 8192;

    // prologue: prestage chunk 0 of call 0 (overlaps z gather)
    if (tidg == 0) {
        mbar_expect(mb, CHUNKB);
        bulk_g2s(obsg, callB[0], CHUNKB, mb);
    }

    stage_a32(smc, OAZ, z, ss, tid);
    __syncthreads();

    float c[2][4][4];

    // ---- GEMM1: a = z @ Wz^T + bz -> a2 (fp16); group N-half; ck0=0 ----
    {
        const int n0 = gid * 128;
        gemm_nc(aZ, obsg, mb, gid, 0, callB[0], callB[1], c, tidg);
        const float* bzp = bz + (size_t)e * Zn + n0;
#pragma unroll
        for (int mt = 0; mt < 2; mt++) {
            const int r0 = wm * 32 + mt * 16 + t4;
#pragma unroll
            for (int nt = 0; nt < 4; nt++) {
                const int col = wn * 32 + nt * 8 + t2;
                const float2 bb = *(const float2*)(bzp + col);
                uint32_t o = (uint32_t)(r0 * LDA + n0 + col) * 2;
                *(__half2*)(smc + OA2 + o) = __floats2half2_rn(c[mt][nt][0] + bb.x, c[mt][nt][1] + bb.y);
                o = (uint32_t)((r0 + 8) * LDA + n0 + col) * 2;
                *(__half2*)(smc + OA2 + o) = __floats2half2_rn(c[mt][nt][2] + bb.x, c[mt][nt][3] + bb.y);
            }
        }
    }
    __syncthreads();

    stage_a32(smc, OAZ, u, ss, tid);
    __syncthreads();

    // ---- GEMM2: h = relu(a @ Wh^T + bh) -> out; ck0 = 2..8 ----
    {
        for (int nc = 0; nc < 4; nc++) {
            const int n0 = nc * 256 + gid * 128;
            gemm_nc(a2, obsg, mb, gid, 2 + nc * 2, callB[1 + nc], callB[2 + nc], c, tidg);
            const float* bhp = bhb + (size_t)e * Hn + n0;
#pragma unroll
            for (int mt = 0; mt < 2; mt++) {
                const int r0 = wm * 32 + mt * 16 + t4;
                const int s0 = ss[r0], s1 = ss[r0 + 8];
#pragma unroll
                for (int nt = 0; nt < 4; nt++) {
                    const int col = wn * 32 + nt * 8 + t2;
                    const float2 bb = *(const float2*)(bhp + col);
                    if (s0 >= 0) {
                        float2 o;
                        o.x = fmaxf(c[mt][nt][0] + bb.x, 0.f);
                        o.y = fmaxf(c[mt][nt][1] + bb.y, 0.f);
                        *(float2*)(out + (size_t)s0 * Hn + n0 + col) = o;
                    }
                    if (s1 >= 0) {
                        float2 o;
                        o.x = fmaxf(c[mt][nt][2] + bb.x, 0.f);
                        o.y = fmaxf(c[mt][nt][3] + bb.y, 0.f);
                        *(float2*)(out + (size_t)s1 * Hn + n0 + col) = o;
                    }
                }
            }
        }
    }

    // ---- GEMM3: v = u @ Wu^T -> out + Bn*Hn; ck0 = 10, final ----
    {
        const int n0 = gid * 128;
        float* outv = out + (size_t)Bn * Hn;
        gemm_nc(aZ, obsg, mb, gid, 10, callB[5], nullptr, c, tidg);
#pragma unroll
        for (int mt = 0; mt < 2; mt++) {
            const int r0 = wm * 32 + mt * 16 + t4;
            const int s0 = ss[r0], s1 = ss[r0 + 8];
#pragma unroll
            for (int nt = 0; nt < 4; nt++) {
                const int col = wn * 32 + nt * 8 + t2;
                if (s0 >= 0) {
                    float2 o; o.x = c[mt][nt][0]; o.y = c[mt][nt][1];
                    *(float2*)(outv + (size_t)s0 * Un + n0 + col) = o;
                }
                if (s1 >= 0) {
                    float2 o; o.x = c[mt][nt][2]; o.y = c[mt][nt][3];
                    *(float2*)(outv + (size_t)s1 * Un + n0 + col) = o;
                }
            }
        }
    }
}

// ---------------- launcher ----------------
extern "C" void kernel_launch(void* const* d_in, const int* in_sizes, int n_in,
                              void* d_out, int out_size) {
    (void)in_sizes; (void)n_in; (void)out_size;
    const float* z   = (const float*)d_in[0];
    const float* u   = (const float*)d_in[1];
    const int*   rng = (const int*)d_in[2];
    const float* Wz  = (const float*)d_in[3];
    const float* bz  = (const float*)d_in[4];
    const float* Wh  = (const float*)d_in[5];
    const float* bh  = (const float*)d_in[6];
    const float* Wu  = (const float*)d_in[7];
    float* out = (float*)d_out;

    cudaFuncSetAttribute(k_moe, cudaFuncAttributeMaxDynamicSharedMemorySize, SMEM_DYN);

    k_pre<<<CVB + 1, NTPRE>>>(rng, Wz, Wh, Wu);
    k_moe<<<MAXT, NT, SMEM_DYN>>>(z, u, bz, bh, out);
}

// round 17
// speedup vs baseline: 1.1359x; 1.0354x over previous
#include <cuda_runtime.h>
#include <cuda_fp16.h>
#include <cstdint>

#define Bn 8192
#define En 16
#define Zn 256
#define Hn 1024
#define Un 256
#define TM 64
#define MAXT 144
#define NT 512
#define NTPRE 512
#define TILEB 16384                // 16KB sub-tile: 128 rows x 64 halves, swizzled
#define CHUNK 32768                // one (call,kc) chunk: 256 rows x 64 halves
#define TPE 48                     // tiles/expert: Wz 8, Wh 32, Wu 8 (kc-major)

// smem byte offsets (A tiles swizzled 512B rows, 32KB each)
#define OAZ 0
#define OAU 32768
#define OA2 65536
#define OBS 98304                  // B buffers: group g at OBS + g*2*CHUNK
#define SMEM_DYN (OBS + 4*CHUNK)   // 229376

// ---------------- device scratch ----------------
__device__ int g_perm[Bn];
__device__ int g_te[MAXT], g_ts[MAXT], g_tr[MAXT];
__device__ int g_ntiles;
__device__ __half g_Wt[(size_t)En * TPE * 8192];

// ---------------- helpers ----------------
__device__ __forceinline__ uint32_t s2u(const void* p) {
    uint32_t a;
    asm("{ .reg .u64 t; cvta.to.shared.u64 t, %1; cvt.u32.u64 %0, t; }" : "=r"(a) : "l"(p));
    return a;
}
__device__ __forceinline__ void mbar_init(uint32_t a, uint32_t c) {
    asm volatile("mbarrier.init.shared.b64 [%0], %1;" :: "r"(a), "r"(c) : "memory");
}
__device__ __forceinline__ void mbar_expect(uint32_t a, uint32_t bytes) {
    asm volatile("mbarrier.arrive.expect_tx.shared.b64 _, [%0], %1;" :: "r"(a), "r"(bytes) : "memory");
}
__device__ __forceinline__ void bulk_g2s(uint32_t dst, const void* src, uint32_t bytes, uint32_t mbar) {
    asm volatile("cp.async.bulk.shared::cluster.global.mbarrier::complete_tx::bytes [%0], [%1], %2, [%3];"
                 :: "r"(dst), "l"(src), "r"(bytes), "r"(mbar) : "memory");
}
__device__ __forceinline__ void mwait(uint32_t a, uint32_t par) {
    uint32_t done = 0;
    while (!done) {
        asm volatile("{ .reg .pred p; mbarrier.try_wait.parity.acquire.cta.shared::cta.b64 p, [%1], %2; selp.b32 %0, 1, 0, p; }"
                     : "=r"(done) : "r"(a), "r"(par) : "memory");
    }
}
__device__ __forceinline__ void gbar(int id) {
    asm volatile("bar.sync %0, 256;" :: "r"(id) : "memory");
}
__device__ __forceinline__ void ldm4(uint32_t r[4], uint32_t addr) {
    asm volatile("ldmatrix.sync.aligned.m8n8.x4.shared.b16 {%0,%1,%2,%3}, [%4];"
                 : "=r"(r[0]), "=r"(r[1]), "=r"(r[2]), "=r"(r[3]) : "r"(addr));
}
__device__ __forceinline__ void mma16816(float c[4], const uint32_t a[4], uint32_t b0, uint32_t b1) {
    asm volatile("mma.sync.aligned.m16n8k16.row.col.f32.f16.f16.f32 "
                 "{%0,%1,%2,%3}, {%4,%5,%6,%7}, {%8,%9}, {%0,%1,%2,%3};"
                 : "+f"(c[0]), "+f"(c[1]), "+f"(c[2]), "+f"(c[3])
                 : "r"(a[0]), "r"(a[1]), "r"(a[2]), "r"(a[3]), "r"(b0), "r"(b1));
}
// A: swizzled 512B rows (32 16B-units), B sub-tile: swizzled 128B rows
__device__ __forceinline__ uint32_t swA(uint32_t r, uint32_t c16) {
    return (r << 9) + ((c16 >> 3) << 7) + (((c16 & 7) ^ (r & 7)) << 4);
}
__device__ __forceinline__ uint32_t swB(uint32_t r, uint32_t c16) {
    return (r << 7) + (((c16) ^ (r & 7)) << 4);
}

// convert one 16B dest unit of swizzled weight tile (kc-major layout)
__device__ __forceinline__ void cvt_unit(int id, const float* __restrict__ Wz,
                                         const float* __restrict__ Wh,
                                         const float* __restrict__ Wu) {
    const int t = id >> 10;
    const int w = id & 1023;
    const int r = w >> 3, c16s = w & 7;
    const int e = t / TPE, s = t % TPE;
    const float* src; int nc, kc;
    if (s < 8)       { src = Wz + (size_t)e * Zn * Zn; kc = s >> 1;        nc = s & 1; }
    else if (s < 40) { src = Wh + (size_t)e * Hn * Zn; kc = (s - 8) >> 3;  nc = (s - 8) & 7; }
    else             { src = Wu + (size_t)e * Un * Un; kc = (s - 40) >> 1; nc = (s - 40) & 1; }
    const int n = nc * 128 + r;
    const int k = kc * 64 + ((c16s ^ (r & 7)) << 3);
    const float4* sp = (const float4*)(src + (size_t)n * 256 + k);
    const float4 v0 = __ldg(sp), v1 = __ldg(sp + 1);
    union { __half2 h[4]; uint4 q; } P;
    P.h[0] = __floats2half2_rn(v0.x, v0.y);
    P.h[1] = __floats2half2_rn(v0.z, v0.w);
    P.h[2] = __floats2half2_rn(v1.x, v1.y);
    P.h[3] = __floats2half2_rn(v1.z, v1.w);
    *(uint4*)((char*)g_Wt + (size_t)t * TILEB + (uint32_t)((r << 7) + (c16s << 4))) = P.q;
}

// ---------------- k_pre: fat cvt blocks + setup block ----------------
#define NUNITS (En*TPE*1024)
#define CVB (NUNITS/(NTPRE*4))     // 384

__global__ __launch_bounds__(NTPRE) void k_pre(const int* __restrict__ rng,
                                               const float* __restrict__ Wz,
                                               const float* __restrict__ Wh,
                                               const float* __restrict__ Wu) {
    if (blockIdx.x == CVB) {
        __shared__ int srng[Bn];
        __shared__ int sc[En], soff[En], scur[En];
        const int tid = threadIdx.x, lane = tid & 31;
        for (int i = tid; i < Bn; i += NTPRE) srng[i] = rng[i];
        if (tid < En) { sc[tid] = 0; scur[tid] = 0; }
        __syncthreads();
        for (int i = tid; i < Bn; i += NTPRE) {
            int e = srng[i];
            unsigned m = __match_any_sync(0xffffffffu, e);
            if (lane == __ffs(m) - 1) atomicAdd(&sc[e], __popc(m));
        }
        __syncthreads();
        if (tid == 0) {
            int acc = 0, nt = 0;
            for (int e = 0; e < En; e++) {
                soff[e] = acc;
                int c = sc[e];
                for (int s = 0; s < c; s += TM) {
                    g_te[nt] = e;
                    g_ts[nt] = acc + s;
                    g_tr[nt] = (c - s) < TM ? (c - s) : TM;
                    nt++;
                }
                acc += c;
            }
            g_ntiles = nt;
        }
        __syncthreads();
        for (int i = tid; i < Bn; i += NTPRE) {
            int e = srng[i];
            unsigned m = __match_any_sync(0xffffffffu, e);
            int leader = __ffs(m) - 1;
            int rank = __popc(m & ((1u << lane) - 1u));
            int base = 0;
            if (lane == leader) base = atomicAdd(&scur[e], __popc(m));
            base = __shfl_sync(0xffffffffu, base, leader);
            g_perm[soff[e] + base + rank] = i;
        }
        return;
    }
    const int base = blockIdx.x * (NTPRE * 4) + threadIdx.x;
    cvt_unit(base,             Wz, Wh, Wu);
    cvt_unit(base + NTPRE,     Wz, Wh, Wu);
    cvt_unit(base + 2 * NTPRE, Wz, Wh, Wu);
    cvt_unit(base + 3 * NTPRE, Wz, Wh, Wu);
}

// ---------------- A staging: 64 gathered fp32 rows -> swizzled fp16 (256 thr) ----------------
__device__ __forceinline__ void stage_a32g(char* smc, int off, const float* __restrict__ g,
                                           const int* ss, int tidg) {
#pragma unroll
    for (int i = tidg; i < TM * 32; i += 256) {
        int r = i >> 5, c16 = i & 31;
        int s = ss[r];
        uint4 q = make_uint4(0u, 0u, 0u, 0u);
        if (s >= 0) {
            const float4 v0 = __ldg((const float4*)(g + (size_t)s * 256 + c16 * 8));
            const float4 v1 = __ldg((const float4*)(g + (size_t)s * 256 + c16 * 8 + 4));
            union { __half2 h[4]; uint4 u; } P;
            P.h[0] = __floats2half2_rn(v0.x, v0.y);
            P.h[1] = __floats2half2_rn(v0.z, v0.w);
            P.h[2] = __floats2half2_rn(v1.x, v1.y);
            P.h[3] = __floats2half2_rn(v1.z, v1.w);
            q = P.u;
        }
        *(uint4*)(smc + off + swA((uint32_t)r, (uint32_t)c16)) = q;
    }
}

// ---------------- group GEMM: one 64x256 output call, KC=64 x 4 chunks ----------------
// Warp tile 32x64 (8 warps 2x4). Chunks staged via cp.async.bulk 32KB; 2-buffer
// ring; global per-group chunk index ck=ck0+kc, buffer=ck&1, parity=(ck>>1)&1.
// Chunk kc address: gB + kc*kstr (halves). gBnext = next call's chunk 0.
__device__ __forceinline__ void gemm_call(uint32_t aB, uint32_t obsg, uint32_t mb, int gid,
                                          int ck0, const __half* __restrict__ gB, size_t kstr,
                                          const __half* __restrict__ gBnext,
                                          float c[2][8][4], int tidg) {
    const int lane = tidg & 31, wig = tidg >> 5;
    const int wm = wig >> 2, wn = wig & 3;
    const int lrow = (lane & 7) + ((lane >> 3) & 1) * 8;
    const int l16  = lane >> 4;

#pragma unroll
    for (int mt = 0; mt < 2; mt++)
#pragma unroll
        for (int nt = 0; nt < 8; nt++)
#pragma unroll
            for (int j = 0; j < 4; j++) c[mt][nt][j] = 0.f;

#pragma unroll
    for (int kc = 0; kc < 4; kc++) {
        const int ck = ck0 + kc;
        mwait(mb + (uint32_t)(ck & 1) * 8, (uint32_t)((ck >> 1) & 1));
        gbar(1 + gid);
        const __half* nsrc = (kc < 3) ? (gB + (size_t)(kc + 1) * kstr) : gBnext;
        if (nsrc && tidg == 0) {
            const uint32_t b1 = (uint32_t)((ck + 1) & 1);
            mbar_expect(mb + b1 * 8, CHUNK);
            bulk_g2s(obsg + b1 * CHUNK, nsrc, CHUNK, mb + b1 * 8);
        }

        const uint32_t bH = obsg + (uint32_t)(ck & 1) * CHUNK;
#pragma unroll
        for (int k16 = 0; k16 < 4; k16++) {
            const uint32_t au = (uint32_t)(kc * 8 + k16 * 2 + l16);
            uint32_t ah[2][4];
#pragma unroll
            for (int mt = 0; mt < 2; mt++)
                ldm4(ah[mt], aB + swA((uint32_t)(wm * 32 + mt * 16 + lrow), au));
            uint32_t bf[4][4];
#pragma unroll
            for (int ng = 0; ng < 4; ng++) {
                const uint32_t rows = (uint32_t)(wn * 64 + ng * 16 + lrow);
                ldm4(bf[ng], bH + ((rows >> 7) << 14)
                             + swB(rows & 127u, (uint32_t)(k16 * 2 + l16)));
            }
#pragma unroll
            for (int mt = 0; mt < 2; mt++)
#pragma unroll
                for (int nt = 0; nt < 8; nt++)
                    mma16816(c[mt][nt], ah[mt], bf[nt >> 1][nt & 1], bf[nt >> 1][(nt & 1) + 2]);
        }
    }
}

// ---------------- fused MoE kernel (call-specialized groups) ----------------
__global__ __launch_bounds__(NT, 1)
void k_moe(const float* __restrict__ z, const float* __restrict__ u,
           const float* __restrict__ bz, const float* __restrict__ bhb,
           float* __restrict__ out) {
    const int bt = blockIdx.x;
    if (bt >= g_ntiles) return;
    const int e = g_te[bt], start = g_ts[bt], rows = g_tr[bt];
    const int tid = threadIdx.x;
    const int gid = tid >> 8;
    const int tidg = tid & 255;
    const int lane = tid & 31, wig = tidg >> 5;
    const int wm = wig >> 2, wn = wig & 3;
    const int t4 = lane >> 2, t2 = (lane & 3) * 2;

    extern __shared__ char smc[];
    const uint32_t sm0 = s2u(smc);
    const uint32_t aZ = sm0 + OAZ, aU = sm0 + OAU, a2 = sm0 + OA2;
    const uint32_t obsg = sm0 + OBS + (uint32_t)gid * 2 * CHUNK;

    __shared__ __align__(8) unsigned long long s_mb[4];
    const uint32_t mb = s2u(s_mb) + (uint32_t)gid * 16;

    __shared__ int ss[TM];
    if (tid < TM) ss[tid] = (tid < rows) ? g_perm[start + tid] : -1;
    if (tid < 4) mbar_init(s2u(s_mb) + tid * 8, 1);
    __syncthreads();

    // kc-major weight bases (halves)
    const __half* Wbase = g_Wt + (size_t)e * TPE * 8192;
    const __half* Wzb = Wbase;                       // 8 tiles  [kc*2+nc]
    const __half* Whb = Wbase + (size_t)8 * 8192;    // 32 tiles [kc*8+nc]
    const __half* Wub = Wbase + (size_t)40 * 8192;   // 8 tiles  [kc*2+nc]

    // group call plan:
    //   g0: GEMM1 (Wz, kstr 2*8192) -> GEMM2 c0 -> GEMM2 c1
    //   g1: GEMM3 (Wu, kstr 2*8192) -> GEMM2 c2 -> GEMM2 c3
    const __half* callB[3]; size_t kstr[3];
    if (gid == 0) {
        callB[0] = Wzb;                 kstr[0] = 2 * 8192;
        callB[1] = Whb;                 kstr[1] = 8 * 8192;
        callB[2] = Whb + 2 * 8192;      kstr[2] = 8 * 8192;
    } else {
        callB[0] = Wub;                 kstr[0] = 2 * 8192;
        callB[1] = Whb + 4 * 8192;      kstr[1] = 8 * 8192;
        callB[2] = Whb + 6 * 8192;      kstr[2] = 8 * 8192;
    }

    // prologue: each group prestages its call0 chunk0
    if (tidg == 0) {
        mbar_expect(mb, CHUNK);
        bulk_g2s(obsg, callB[0], CHUNK, mb);
    }
    // g0 stages z, g1 stages u (self-consumed; first gbar orders it)
    stage_a32g(smc, gid == 0 ? OAZ : OAU, gid == 0 ? z : u, ss, tidg);

    float c[2][8][4];

    // ---- call 0: g0 GEMM1 -> a2 ; g1 GEMM3 -> outv ----
    gemm_call(gid == 0 ? aZ : aU, obsg, mb, gid, 0, callB[0], kstr[0], callB[1], c, tidg);
    if (gid == 0) {
        const float* bzp = bz + (size_t)e * Zn;
#pragma unroll
        for (int mt = 0; mt < 2; mt++) {
            const uint32_t r0 = (uint32_t)(wm * 32 + mt * 16 + t4);
#pragma unroll
            for (int nt = 0; nt < 8; nt++) {
                const int col = wn * 64 + nt * 8 + t2;
                const float2 bb = *(const float2*)(bzp + col);
                const uint32_t u16 = (uint32_t)(col >> 3);
                *(__half2*)(smc + OA2 + swA(r0, u16) + t2 * 2) =
                    __floats2half2_rn(c[mt][nt][0] + bb.x, c[mt][nt][1] + bb.y);
                *(__half2*)(smc + OA2 + swA(r0 + 8, u16) + t2 * 2) =
                    __floats2half2_rn(c[mt][nt][2] + bb.x, c[mt][nt][3] + bb.y);
            }
        }
    } else {
        float* outv = out + (size_t)Bn * Hn;
#pragma unroll
        for (int mt = 0; mt < 2; mt++) {
            const int r0 = wm * 32 + mt * 16 + t4;
            const int s0 = ss[r0], s1 = ss[r0 + 8];
#pragma unroll
            for (int nt = 0; nt < 8; nt++) {
                const int col = wn * 64 + nt * 8 + t2;
                if (s0 >= 0) {
                    float2 o; o.x = c[mt][nt][0]; o.y = c[mt][nt][1];
                    *(float2*)(outv + (size_t)s0 * Un + col) = o;
                }
                if (s1 >= 0) {
                    float2 o; o.x = c[mt][nt][2]; o.y = c[mt][nt][3];
                    *(float2*)(outv + (size_t)s1 * Un + col) = o;
                }
            }
        }
    }
    __syncthreads();   // a2 complete & visible to both groups

    // ---- calls 1,2: GEMM2 chunks (g0: c0,c1 ; g1: c2,c3) ----
#pragma unroll
    for (int j = 0; j < 2; j++) {
        const int cg = gid * 2 + j;                       // global GEMM2 call 0..3
        const int n0 = cg * 256;
        gemm_call(a2, obsg, mb, gid, 4 + j * 4, callB[1 + j], kstr[1 + j],
                  (j == 0) ? callB[2] : nullptr, c, tidg);
        const float* bhp = bhb + (size_t)e * Hn + n0;
#pragma unroll
        for (int mt = 0; mt < 2; mt++) {
            const int r0 = wm * 32 + mt * 16 + t4;
            const int s0 = ss[r0], s1 = ss[r0 + 8];
#pragma unroll
            for (int nt = 0; nt < 8; nt++) {
                const int col = wn * 64 + nt * 8 + t2;
                const float2 bb = *(const float2*)(bhp + col);
                if (s0 >= 0) {
                    float2 o;
                    o.x = fmaxf(c[mt][nt][0] + bb.x, 0.f);
                    o.y = fmaxf(c[mt][nt][1] + bb.y, 0.f);
                    *(float2*)(out + (size_t)s0 * Hn + n0 + col) = o;
                }
                if (s1 >= 0) {
                    float2 o;
                    o.x = fmaxf(c[mt][nt][2] + bb.x, 0.f);
                    o.y = fmaxf(c[mt][nt][3] + bb.y, 0.f);
                    *(float2*)(out + (size_t)s1 * Hn + n0 + col) = o;
                }
            }
        }
    }
}

// ---------------- launcher ----------------
extern "C" void kernel_launch(void* const* d_in, const int* in_sizes, int n_in,
                              void* d_out, int out_size) {
    (void)in_sizes; (void)n_in; (void)out_size;
    const float* z   = (const float*)d_in[0];
    const float* u   = (const float*)d_in[1];
    const int*   rng = (const int*)d_in[2];
    const float* Wz  = (const float*)d_in[3];
    const float* bz  = (const float*)d_in[4];
    const float* Wh  = (const float*)d_in[5];
    const float* bh  = (const float*)d_in[6];
    const float* Wu  = (const float*)d_in[7];
    float* out = (float*)d_out;

    cudaFuncSetAttribute(k_moe, cudaFuncAttributeMaxDynamicSharedMemorySize, SMEM_DYN);

    k_pre<<<CVB + 1, NTPRE>>>(rng, Wz, Wh, Wu);
    k_moe<<<MAXT, NT, SMEM_DYN>>>(z, u, bz, bh, out);
}